// round 1
// baseline (speedup 1.0000x reference)
#include <cuda_runtime.h>
#include <cstdint>

// ---------------------------------------------------------------------------
// Problem constants
// ---------------------------------------------------------------------------
#define NUM_CLASSES 80
#define B_IMG 8
#define NTOT 20460            // total anchors per image across 5 levels
#define TOPK 1000
#define MAX_PER_IMG 100
#define IMG_H 768.0f
#define IMG_W 1280.0f
#define CLS_OFFSET 4096.0f
#define MAX_RATIO_ANCHOR 13.815510557964274f   // |log(1e-6)|
#define MAX_RATIO_BBOX   4.135166556742356f    // |log(16/1000)|

__device__ __constant__ int   c_HW[5]     = {15360, 3840, 960, 240, 60};
__device__ __constant__ int   c_W[5]      = {160, 80, 40, 20, 10};
__device__ __constant__ int   c_off[5]    = {0, 15360, 19200, 20160, 20400};
__device__ __constant__ float c_stride[5] = {8.f, 16.f, 32.f, 64.f, 128.f};

// ---------------------------------------------------------------------------
// Scratch (device globals; no runtime allocation allowed)
// ---------------------------------------------------------------------------
__device__ float  g_key[B_IMG * NTOT];          // per-anchor masked max score
__device__ int    g_sel[B_IMG * 1024];          // selected anchor ids (sorted)
__device__ float  g_sc[B_IMG * NUM_CLASSES * 1024]; // class-major scores, thresholded
__device__ float4 g_boxes[B_IMG * 1024];        // decoded proposals

struct Ptrs { const float* p[20]; };

// ---------------------------------------------------------------------------
// Numerics matching jax
// ---------------------------------------------------------------------------
__device__ __forceinline__ float sigf(float x) {
    if (x >= 0.f) return 1.f / (1.f + expf(-x));
    float e = expf(x);
    return e / (1.f + e);
}
__device__ __forceinline__ float dsigf(float x) {
    float s = sigf(x);              // s in (0,1) -> non-negative branch
    return 1.f / (1.f + expf(-s));
}
__device__ __forceinline__ float clampf(float v, float lo, float hi) {
    return fminf(fmaxf(v, lo), hi);
}

// ---------------------------------------------------------------------------
// Kernel 1: per-anchor masked max-class score (key for top-k)
// ---------------------------------------------------------------------------
__global__ __launch_bounds__(256) void k_maxscore(Ptrs P) {
    int b = blockIdx.y;
    int a = blockIdx.x * 256 + threadIdx.x;
    if (a >= NTOT) return;

    int l;
    if      (a < 15360) l = 0;
    else if (a < 19200) l = 1;
    else if (a < 20160) l = 2;
    else if (a < 20400) l = 3;
    else                l = 4;
    int r  = a - c_off[l];
    int HW = c_HW[l];

    const float* loc = P.p[4 * l + 3];
    float key = 0.f;
    float ls = sigf(loc[(size_t)b * HW + r]);
    if (ls >= 0.01f) {
        const float* cp = P.p[4 * l] + ((size_t)b * NUM_CLASSES) * HW + r;
        float m = -3.402823466e38f;
        #pragma unroll 8
        for (int c = 0; c < NUM_CLASSES; c++)
            m = fmaxf(m, cp[(size_t)c * HW]);
        key = dsigf(m);
    }
    g_key[(size_t)b * NTOT + a] = key;
}

// ---------------------------------------------------------------------------
// Kernel 2: per-image top-1000 by (key desc, idx asc). Radix-select threshold
// then stable compaction, then 1024-wide bitonic sort of composites.
// ---------------------------------------------------------------------------
__global__ __launch_bounds__(1024) void k_select() {
    int b   = blockIdx.x;
    int tid = threadIdx.x;
    int lane = tid & 31, wid = tid >> 5;
    const unsigned* keys = reinterpret_cast<const unsigned*>(g_key) + (size_t)b * NTOT;

    __shared__ unsigned hist[256];
    __shared__ unsigned s_prefix;
    __shared__ int s_m;
    __shared__ unsigned long long sel[1024];
    __shared__ int warp_tot[32];
    __shared__ int warp_scan[32];
    __shared__ int s_fill;
    __shared__ int s_runeq;

    if (tid == 0) { s_prefix = 0u; s_m = TOPK; }
    __syncthreads();

    // --- 4-round radix select (8 bits per round) to find threshold T ---
    for (int round = 0; round < 4; round++) {
        int shift = 24 - 8 * round;
        unsigned kmask = (round == 0) ? 0u : (0xFFFFFFFFu << (32 - 8 * round));
        if (tid < 256) hist[tid] = 0u;
        __syncthreads();
        unsigned pfx = s_prefix;
        for (int i = tid; i < NTOT; i += 1024) {
            unsigned k = keys[i];
            if ((k & kmask) == pfx) atomicAdd(&hist[(k >> shift) & 0xFFu], 1u);
        }
        __syncthreads();
        if (tid == 0) {
            int m = s_m;
            unsigned cum = 0;
            for (int bin = 255; bin >= 0; bin--) {
                unsigned h = hist[bin];
                if (cum + h >= (unsigned)m) {
                    s_prefix = pfx | ((unsigned)bin << shift);
                    s_m = m - (int)cum;
                    break;
                }
                cum += h;
            }
        }
        __syncthreads();
    }
    unsigned T = s_prefix;
    int meq = s_m;                          // how many ==T to take (by index order)

    sel[tid] = 0ull;
    if (tid == 0) { s_fill = 0; s_runeq = 0; }
    __syncthreads();

    // --- compaction: all >T (order irrelevant, sorted later); first meq ==T ---
    for (int base = 0; base < NTOT; base += 1024) {
        int i = base + tid;
        bool valid = i < NTOT;
        unsigned k = valid ? keys[i] : 0u;
        bool gt = valid && (k > T);
        bool eq = valid && (k == T);
        if (gt) {
            int p = atomicAdd(&s_fill, 1);
            sel[p] = (((unsigned long long)k) << 32) |
                     (unsigned long long)(0xFFFFFFFFu - (unsigned)i);
        }
        unsigned bal = __ballot_sync(0xFFFFFFFFu, eq);
        if (lane == 0) warp_tot[wid] = __popc(bal);
        __syncthreads();
        if (wid == 0) {
            int v = warp_tot[lane];
            #pragma unroll
            for (int d = 1; d < 32; d <<= 1) {
                int n = __shfl_up_sync(0xFFFFFFFFu, v, d);
                if (lane >= d) v += n;
            }
            warp_scan[lane] = v;            // inclusive scan
        }
        __syncthreads();
        int wbase = (wid == 0) ? 0 : warp_scan[wid - 1];
        int rank = s_runeq + wbase + __popc(bal & ((1u << lane) - 1u));
        if (eq && rank < meq) {
            int p = atomicAdd(&s_fill, 1);
            sel[p] = (((unsigned long long)k) << 32) |
                     (unsigned long long)(0xFFFFFFFFu - (unsigned)i);
        }
        __syncthreads();
        if (tid == 0) s_runeq += warp_scan[31];
        __syncthreads();
    }

    // --- bitonic sort descending on composite (key desc, idx asc) ---
    for (int k2 = 2; k2 <= 1024; k2 <<= 1) {
        for (int j = k2 >> 1; j > 0; j >>= 1) {
            __syncthreads();
            int ixj = tid ^ j;
            if (ixj > tid) {
                unsigned long long va = sel[tid], vb = sel[ixj];
                bool up = ((tid & k2) == 0);
                if (up ? (va < vb) : (va > vb)) { sel[tid] = vb; sel[ixj] = va; }
            }
        }
    }
    __syncthreads();
    g_sel[b * 1024 + tid] = (int)(0xFFFFFFFFu - (unsigned)(sel[tid] & 0xFFFFFFFFull));
}

// ---------------------------------------------------------------------------
// Kernel 3: gather per-class scores (thresholded) + decode proposal box
// one warp per selected row
// ---------------------------------------------------------------------------
__global__ __launch_bounds__(256) void k_gather(Ptrs P) {
    int w = (blockIdx.x * 256 + threadIdx.x) >> 5;
    int lane = threadIdx.x & 31;
    if (w >= B_IMG * TOPK) return;
    int b = w / TOPK;
    int j = w - b * TOPK;
    int a = g_sel[b * 1024 + j];

    int l;
    if      (a < 15360) l = 0;
    else if (a < 19200) l = 1;
    else if (a < 20160) l = 2;
    else if (a < 20400) l = 3;
    else                l = 4;
    int r  = a - c_off[l];
    int HW = c_HW[l];
    int W  = c_W[l];
    int yi = r / W;
    int xi = r - yi * W;

    const float* cls = P.p[4 * l + 0];
    const float* bb  = P.p[4 * l + 1];
    const float* shp = P.p[4 * l + 2];
    const float* loc = P.p[4 * l + 3];

    float maskf = (sigf(loc[(size_t)b * HW + r]) >= 0.01f) ? 1.f : 0.f;

    for (int c = lane; c < NUM_CLASSES; c += 32) {
        float v = cls[((size_t)b * NUM_CLASSES + c) * HW + r];
        float s = maskf * dsigf(v);
        g_sc[((size_t)b * NUM_CLASSES + c) * 1024 + j] = (s > 0.05f) ? s : 0.f;
    }

    if (lane == 0) {
        float st = c_stride[l];
        float xx = (float)xi * st, yy = (float)yi * st;
        float pw = 4.f * st;
        // guided anchor (delta2bbox with [0,0,dw,dh])
        float dw = clampf(shp[((size_t)b * 2 + 0) * HW + r], -MAX_RATIO_ANCHOR, MAX_RATIO_ANCHOR);
        float dh = clampf(shp[((size_t)b * 2 + 1) * HW + r], -MAX_RATIO_ANCHOR, MAX_RATIO_ANCHOR);
        float aw = pw * expf(dw);
        float ah = pw * expf(dh);
        float ax1 = xx - 0.5f * aw, ay1 = yy - 0.5f * ah;
        float ax2 = xx + 0.5f * aw, ay2 = yy + 0.5f * ah;
        // bbox decode (delta2bbox, clipped to image)
        float px = (ax1 + ax2) * 0.5f, py = (ay1 + ay2) * 0.5f;
        float w2 = ax2 - ax1,          h2 = ay2 - ay1;
        float dx  = bb[((size_t)b * 4 + 0) * HW + r];
        float dy  = bb[((size_t)b * 4 + 1) * HW + r];
        float dw2 = clampf(bb[((size_t)b * 4 + 2) * HW + r], -MAX_RATIO_BBOX, MAX_RATIO_BBOX);
        float dh2 = clampf(bb[((size_t)b * 4 + 3) * HW + r], -MAX_RATIO_BBOX, MAX_RATIO_BBOX);
        float gx = px + w2 * dx;
        float gy = py + h2 * dy;
        float gw = w2 * expf(dw2);
        float gh = h2 * expf(dh2);
        float x1 = clampf(gx - 0.5f * gw, 0.f, IMG_W);
        float y1 = clampf(gy - 0.5f * gh, 0.f, IMG_H);
        float x2 = clampf(gx + 0.5f * gw, 0.f, IMG_W);
        float y2 = clampf(gy + 0.5f * gh, 0.f, IMG_H);
        g_boxes[b * 1024 + j] = make_float4(x1, y1, x2, y2);
    }
}

// ---------------------------------------------------------------------------
// Kernel 4: class-aware greedy NMS, one block per image.
// Maintains per-class (max score, argmin-row-on-tie); suppression only
// touches the picked class (cross-class IoU is 0 by construction, offsets
// >= 4096 > image extent). IoU computed on OFFSET boxes to match reference
// float rounding exactly.
// ---------------------------------------------------------------------------
__global__ __launch_bounds__(1024) void k_nms(float* __restrict__ out) {
    int b = blockIdx.x;
    int tid = threadIdx.x;
    int lane = tid & 31, wid = tid >> 5;

    __shared__ float4 sbox[TOPK];
    __shared__ float cmaxv[NUM_CLASSES];
    __shared__ int   cmaxj[NUM_CLASSES];
    __shared__ float redv[32];
    __shared__ int   redj[32];
    __shared__ float s_curv;
    __shared__ int   s_curc, s_curr;
    __shared__ int   s_ndet;

    if (tid < TOPK) sbox[tid] = g_boxes[b * 1024 + tid];
    if (tid == 0) s_ndet = 0;
    __syncthreads();

    // init per-class maxima: warp `wid` handles classes wid, wid+32, wid+64
    for (int c = wid; c < NUM_CLASSES; c += 32) {
        const float* sp = g_sc + ((size_t)b * NUM_CLASSES + c) * 1024;
        float bv = 0.f; int bj = 0x7FFFFFFF;
        for (int j = lane; j < TOPK; j += 32) {
            float v = sp[j];
            if (v > bv || (v == bv && j < bj)) { bv = v; bj = j; }
        }
        #pragma unroll
        for (int d = 16; d; d >>= 1) {
            float ov = __shfl_down_sync(0xFFFFFFFFu, bv, d);
            int   oj = __shfl_down_sync(0xFFFFFFFFu, bj, d);
            if (ov > bv || (ov == bv && oj < bj)) { bv = ov; bj = oj; }
        }
        if (lane == 0) { cmaxv[c] = bv; cmaxj[c] = bj; }
    }
    __syncthreads();

    float* outB = out + 8;
    float* outS = out + 8 + B_IMG * MAX_PER_IMG * 4;                 // 3208
    float* outC = out + 8 + B_IMG * MAX_PER_IMG * 4 + B_IMG * MAX_PER_IMG; // 4008

    for (int t = 0; t < MAX_PER_IMG; t++) {
        // global best over 80 class maxima (tie: min flattened index r*80+c)
        if (wid == 0) {
            float bv = -1.f; int bkey = 0x7FFFFFFF, bc = 0, br = 0;
            for (int c = lane; c < NUM_CLASSES; c += 32) {
                float v = cmaxv[c];
                int r = cmaxj[c];
                int key = r * NUM_CLASSES + c;
                if (v > bv || (v == bv && key < bkey)) { bv = v; bkey = key; bc = c; br = r; }
            }
            #pragma unroll
            for (int d = 16; d; d >>= 1) {
                float ov = __shfl_down_sync(0xFFFFFFFFu, bv, d);
                int   ok = __shfl_down_sync(0xFFFFFFFFu, bkey, d);
                int   oc = __shfl_down_sync(0xFFFFFFFFu, bc, d);
                int   ob = __shfl_down_sync(0xFFFFFFFFu, br, d);
                if (ov > bv || (ov == bv && ok < bkey)) { bv = ov; bkey = ok; bc = oc; br = ob; }
            }
            if (lane == 0) { s_curv = bv; s_curc = bc; s_curr = br; }
        }
        __syncthreads();
        float v = s_curv;
        int   c = s_curc;
        int   r = s_curr;

        if (tid == 0) {
            bool keep = v > 0.f;
            float kf = keep ? 1.f : 0.f;
            float4 bx = sbox[r];
            int o = b * MAX_PER_IMG + t;
            outB[o * 4 + 0] = bx.x * kf;
            outB[o * 4 + 1] = bx.y * kf;
            outB[o * 4 + 2] = bx.z * kf;
            outB[o * 4 + 3] = bx.w * kf;
            outS[o] = v * kf;
            outC[o] = keep ? (float)c : -1.f;
            if (keep) s_ndet++;
        }

        if (v <= 0.f) {
            // all scores zero -> every remaining step outputs zeros / cls=-1
            __syncthreads();
            for (int tt = t + 1 + tid; tt < MAX_PER_IMG; tt += 1024) {
                int o = b * MAX_PER_IMG + tt;
                outB[o * 4 + 0] = 0.f; outB[o * 4 + 1] = 0.f;
                outB[o * 4 + 2] = 0.f; outB[o * 4 + 3] = 0.f;
                outS[o] = 0.f;
                outC[o] = -1.f;
            }
            break;
        }

        // suppression within class c + recompute its max
        float4 pb = sbox[r];
        float offc = CLS_OFFSET * (float)c;
        float px1 = pb.x + offc, py1 = pb.y + offc;
        float px2 = pb.z + offc, py2 = pb.w + offc;
        float a1 = (px2 - px1) * (py2 - py1);

        float nv = 0.f;
        int nj = tid;
        float* sp = g_sc + ((size_t)b * NUM_CLASSES + c) * 1024;
        if (tid < TOPK) {
            float sj = sp[tid];
            if (sj > 0.f) {
                float4 q = sbox[tid];
                float qx1 = q.x + offc, qy1 = q.y + offc;
                float qx2 = q.z + offc, qy2 = q.w + offc;
                float ltx = fmaxf(px1, qx1), lty = fmaxf(py1, qy1);
                float rbx = fminf(px2, qx2), rby = fminf(py2, qy2);
                float ww = fmaxf(rbx - ltx, 0.f);
                float hh = fmaxf(rby - lty, 0.f);
                float inter = ww * hh;
                float a2 = (qx2 - qx1) * (qy2 - qy1);
                float iou = inter / (a1 + a2 - inter + 1e-6f);
                if (iou > 0.5f) { sj = 0.f; sp[tid] = 0.f; }
            }
            nv = sj;
        }
        #pragma unroll
        for (int d = 16; d; d >>= 1) {
            float ov = __shfl_down_sync(0xFFFFFFFFu, nv, d);
            int   oj = __shfl_down_sync(0xFFFFFFFFu, nj, d);
            if (ov > nv || (ov == nv && oj < nj)) { nv = ov; nj = oj; }
        }
        if (lane == 0) { redv[wid] = nv; redj[wid] = nj; }
        __syncthreads();
        if (wid == 0) {
            nv = redv[lane]; nj = redj[lane];
            #pragma unroll
            for (int d = 16; d; d >>= 1) {
                float ov = __shfl_down_sync(0xFFFFFFFFu, nv, d);
                int   oj = __shfl_down_sync(0xFFFFFFFFu, nj, d);
                if (ov > nv || (ov == nv && oj < nj)) { nv = ov; nj = oj; }
            }
            if (lane == 0) { cmaxv[c] = nv; cmaxj[c] = nj; }
        }
        __syncthreads();
    }

    if (tid == 0) out[b] = (float)s_ndet;
}

// ---------------------------------------------------------------------------
// Launch
// ---------------------------------------------------------------------------
extern "C" void kernel_launch(void* const* d_in, const int* in_sizes, int n_in,
                              void* d_out, int out_size) {
    (void)in_sizes; (void)n_in; (void)out_size;
    Ptrs P;
    for (int i = 0; i < 20; i++) P.p[i] = (const float*)d_in[i];
    float* out = (float*)d_out;

    dim3 g1((NTOT + 255) / 256, B_IMG);
    k_maxscore<<<g1, 256>>>(P);
    k_select<<<B_IMG, 1024>>>();
    k_gather<<<(B_IMG * TOPK * 32 + 255) / 256, 256>>>(P);
    k_nms<<<B_IMG, 1024>>>(out);
}